// round 1
// baseline (speedup 1.0000x reference)
#include <cuda_runtime.h>
#include <cstdint>

#define IN_F   256
#define H_F    64
#define OUT_F  40
#define KSTEPS 10
#define MAX_N  50000
#define MAX_E  800000

// ---------------- scratch (device globals: no allocation allowed) ----------
__device__ __align__(16) float g_A [MAX_N * H_F];   // current h
__device__ __align__(16) float g_B [MAX_N * H_F];   // aggregation accumulator
__device__ __align__(16) float g_h0[MAX_N * H_F];   // teleport state
__device__ float g_deg [MAX_N];
__device__ float g_dinv[MAX_N];
__device__ float g_w  [MAX_E];
__device__ int   g_row[MAX_E];
__device__ int   g_col[MAX_E];
__device__ int   g_idx_is64;

// ---------------- init: zero agg + deg, reset dtype flag -------------------
__global__ void zero_kernel(int N) {
    int i = blockIdx.x * blockDim.x + threadIdx.x;
    if (i < N * H_F) g_B[i] = 0.0f;
    if (i < N)       g_deg[i] = 0.0f;
    if (i == 0)      g_idx_is64 = 1;
}

// ---------------- detect int64 vs int32 edge_index on device ---------------
// int64 values < 2^31 => every odd 32-bit word is 0. int32 data: odd words
// are random node ids in [0, N) -> some nonzero within the scan window.
__global__ void detect_kernel(const int* __restrict__ ei32, int E) {
    int i = blockIdx.x * blockDim.x + threadIdx.x;
    int scan = (E < 100000) ? E : 100000;
    if (i < scan) {
        if (ei32[2 * i + 1] != 0) g_idx_is64 = 0;  // benign race: all write 0
    }
}

// ---------------- edge prep: indices -> int32, in-degree count -------------
__global__ void edge_prep_kernel(const void* __restrict__ ei_raw, int E) {
    int e = blockIdx.x * blockDim.x + threadIdx.x;
    if (e >= E) return;
    int r, c;
    if (g_idx_is64) {
        const long long* ei = (const long long*)ei_raw;
        r = (int)ei[e];
        c = (int)ei[E + e];
    } else {
        const int* ei = (const int*)ei_raw;
        r = ei[e];
        c = ei[E + e];
    }
    g_row[e] = r;
    g_col[e] = c;
    atomicAdd(&g_deg[c], 1.0f);
}

__global__ void dinv_kernel(int N) {
    int i = blockIdx.x * blockDim.x + threadIdx.x;
    if (i < N) g_dinv[i] = rsqrtf(g_deg[i] + 1.0f);  // +1 self-loop
}

__global__ void edge_w_kernel(int E) {
    int e = blockIdx.x * blockDim.x + threadIdx.x;
    if (e < E) g_w[e] = g_dinv[g_row[e]] * g_dinv[g_col[e]];
}

// ---------------- encode: h0 = relu(x@W1 + b1) @ W2 + b2 -------------------
// Block = 256 threads handles 32 rows. x rows staged in smem; W1/W2 read via
// L1 (64KB working set, fully cached, coalesced across the c dimension).
__global__ __launch_bounds__(256) void encode_kernel(
    const float* __restrict__ x,
    const float* __restrict__ W1, const float* __restrict__ b1,
    const float* __restrict__ W2, const float* __restrict__ b2,
    int N)
{
    __shared__ float xs[32][IN_F];   // 32 KB
    __shared__ float ts[32][H_F];    // 8 KB
    int tid  = threadIdx.x;
    int row0 = blockIdx.x * 32;

    // stage x rows (float4, coalesced)
    for (int i = tid; i < 32 * (IN_F / 4); i += 256) {
        int r  = i / (IN_F / 4);
        int k4 = i % (IN_F / 4);
        float4 v = make_float4(0.f, 0.f, 0.f, 0.f);
        if (row0 + r < N)
            v = ((const float4*)x)[(size_t)(row0 + r) * (IN_F / 4) + k4];
        *(float4*)&xs[r][k4 * 4] = v;
    }
    __syncthreads();

    int c  = tid & 63;        // output feature
    int rg = tid >> 6;        // row group 0..3 (8 rows each)

    // ---- stage 1: t = relu(x @ W1 + b1) ----
    float acc[8];
    float bb = b1[c];
    #pragma unroll
    for (int j = 0; j < 8; j++) acc[j] = bb;

    for (int k = 0; k < IN_F; k += 4) {
        float w0 = W1[(k + 0) * H_F + c];
        float w1 = W1[(k + 1) * H_F + c];
        float w2 = W1[(k + 2) * H_F + c];
        float w3 = W1[(k + 3) * H_F + c];
        #pragma unroll
        for (int j = 0; j < 8; j++) {
            float4 xv = *(const float4*)&xs[rg * 8 + j][k];
            acc[j] += xv.x * w0 + xv.y * w1 + xv.z * w2 + xv.w * w3;
        }
    }
    #pragma unroll
    for (int j = 0; j < 8; j++) ts[rg * 8 + j][c] = fmaxf(acc[j], 0.0f);
    __syncthreads();

    // ---- stage 2: h = t @ W2 + b2 ----
    float acc2[8];
    float bb2 = b2[c];
    #pragma unroll
    for (int j = 0; j < 8; j++) acc2[j] = bb2;

    for (int k = 0; k < H_F; k += 4) {
        float w0 = W2[(k + 0) * H_F + c];
        float w1 = W2[(k + 1) * H_F + c];
        float w2 = W2[(k + 2) * H_F + c];
        float w3 = W2[(k + 3) * H_F + c];
        #pragma unroll
        for (int j = 0; j < 8; j++) {
            float4 tv = *(const float4*)&ts[rg * 8 + j][k];
            acc2[j] += tv.x * w0 + tv.y * w1 + tv.z * w2 + tv.w * w3;
        }
    }
    #pragma unroll
    for (int j = 0; j < 8; j++) {
        int r = row0 + rg * 8 + j;
        if (r < N) {
            g_A [r * H_F + c] = acc2[j];
            g_h0[r * H_F + c] = acc2[j];
        }
    }
}

// ---------------- scatter: B[col] += w * A[row]  (vectorized L2 reductions)
// 16 threads per edge, float4 per thread -> 1 red.global.add.v4.f32 each.
__global__ __launch_bounds__(256) void scatter_kernel(int E) {
    int idx = blockIdx.x * blockDim.x + threadIdx.x;
    int e = idx >> 4;
    if (e >= E) return;
    int f = (idx & 15) << 2;
    int r = g_row[e];
    int c = g_col[e];
    float wv = g_w[e];
    float4 v = *(const float4*)(g_A + r * H_F + f);
    float* p = g_B + c * H_F + f;
    asm volatile("red.global.add.v4.f32 [%0], {%1,%2,%3,%4};"
                 :: "l"(p), "f"(v.x * wv), "f"(v.y * wv),
                    "f"(v.z * wv), "f"(v.w * wv)
                 : "memory");
}

// ---------------- combine: A = 0.9*(B + dinv^2 * A) + 0.1*h0 ; B = 0 ------
__global__ __launch_bounds__(256) void combine_kernel(int N) {
    int i = blockIdx.x * blockDim.x + threadIdx.x;  // float4 index
    if (i >= N * (H_F / 4)) return;
    int r = i / (H_F / 4);
    float s  = g_dinv[r];
    float sw = s * s;                       // self-loop weight
    float4 a = ((const float4*)g_A)[i];
    float4 b = ((const float4*)g_B)[i];
    float4 h = ((const float4*)g_h0)[i];
    float4 o;
    o.x = 0.9f * (b.x + sw * a.x) + 0.1f * h.x;
    o.y = 0.9f * (b.y + sw * a.y) + 0.1f * h.y;
    o.z = 0.9f * (b.z + sw * a.z) + 0.1f * h.z;
    o.w = 0.9f * (b.w + sw * a.w) + 0.1f * h.w;
    ((float4*)g_A)[i] = o;
    ((float4*)g_B)[i] = make_float4(0.f, 0.f, 0.f, 0.f);  // rezero for next step
}

// ---------------- decode: out = h @ Wf + bf --------------------------------
__global__ __launch_bounds__(256) void decode_kernel(
    const float* __restrict__ Wf, const float* __restrict__ bf,
    float* __restrict__ out, int N)
{
    __shared__ float hs[32][H_F];            // 8 KB
    __shared__ float wfs[H_F * OUT_F];       // 10 KB
    __shared__ float bfs[OUT_F];
    int tid  = threadIdx.x;
    int row0 = blockIdx.x * 32;

    for (int i = tid; i < H_F * OUT_F; i += 256) wfs[i] = Wf[i];
    if (tid < OUT_F) bfs[tid] = bf[tid];
    for (int i = tid; i < 32 * (H_F / 4); i += 256) {
        int r  = i / (H_F / 4);
        int k4 = i % (H_F / 4);
        float4 v = make_float4(0.f, 0.f, 0.f, 0.f);
        if (row0 + r < N)
            v = ((const float4*)g_A)[(size_t)(row0 + r) * (H_F / 4) + k4];
        *(float4*)&hs[r][k4 * 4] = v;
    }
    __syncthreads();

    for (int e = tid; e < 32 * OUT_F; e += 256) {
        int r = e / OUT_F;
        int o = e % OUT_F;
        if (row0 + r >= N) continue;
        float acc = bfs[o];
        #pragma unroll
        for (int k = 0; k < H_F; k++) acc += hs[r][k] * wfs[k * OUT_F + o];
        out[(size_t)(row0 + r) * OUT_F + o] = acc;
    }
}

// ---------------- launch ---------------------------------------------------
extern "C" void kernel_launch(void* const* d_in, const int* in_sizes, int n_in,
                              void* d_out, int out_size) {
    const float* x  = (const float*)d_in[0];
    const void*  ei = d_in[1];
    const float* W1 = (const float*)d_in[2];
    const float* b1 = (const float*)d_in[3];
    const float* W2 = (const float*)d_in[4];
    const float* b2 = (const float*)d_in[5];
    const float* Wf = (const float*)d_in[6];
    const float* bf = (const float*)d_in[7];
    float* out = (float*)d_out;

    int N = in_sizes[0] / IN_F;   // 50000
    int E = in_sizes[1] / 2;      // 800000

    zero_kernel<<<(N * H_F + 255) / 256, 256>>>(N);
    detect_kernel<<<(100000 + 255) / 256, 256>>>((const int*)ei, E);
    edge_prep_kernel<<<(E + 255) / 256, 256>>>(ei, E);
    dinv_kernel<<<(N + 255) / 256, 256>>>(N);
    edge_w_kernel<<<(E + 255) / 256, 256>>>(E);

    encode_kernel<<<(N + 31) / 32, 256>>>(x, W1, b1, W2, b2, N);

    int scat_blocks = (E * 16 + 255) / 256;
    int comb_blocks = (N * (H_F / 4) + 255) / 256;
    for (int k = 0; k < KSTEPS; k++) {
        scatter_kernel<<<scat_blocks, 256>>>(E);
        combine_kernel<<<comb_blocks, 256>>>(N);
    }

    decode_kernel<<<(N + 31) / 32, 256>>>(Wf, bf, out, N);
}

// round 2
// speedup vs baseline: 1.6996x; 1.6996x over previous
#include <cuda_runtime.h>
#include <cstdint>

#define IN_F   256
#define H_F    64
#define OUT_F  40
#define KSTEPS 10
#define MAX_N  50000
#define MAX_E  800000
#define SCAN_B 1024
#define MAX_BLK ((MAX_N + SCAN_B - 1) / SCAN_B)

// ---------------- scratch (device globals: no allocation allowed) ----------
__device__ __align__(16) float g_A [MAX_N * H_F];   // ping
__device__ __align__(16) float g_B [MAX_N * H_F];   // pong
__device__ __align__(16) float g_h0[MAX_N * H_F];   // teleport state
__device__ int   g_degi[MAX_N];
__device__ float g_dinv[MAX_N];
__device__ int   g_off [MAX_N + 1];
__device__ int   g_cur [MAX_N];
__device__ int   g_bsum[MAX_BLK];
__device__ int2  g_csr [MAX_E];    // {row, w-as-bits}
__device__ int   g_row [MAX_E];
__device__ int   g_col [MAX_E];
__device__ int   g_idx_is64;

// ---------------- init ------------------------------------------------------
__global__ void zero_kernel(int N) {
    int i = blockIdx.x * blockDim.x + threadIdx.x;
    if (i < N) g_degi[i] = 0;
    if (i == 0) g_idx_is64 = 1;
}

// detect int64 vs int32 edge_index: int64 values < 2^31 => odd words all 0
__global__ void detect_kernel(const int* __restrict__ ei32, int E) {
    int i = blockIdx.x * blockDim.x + threadIdx.x;
    int scan = (E < 100000) ? E : 100000;
    if (i < scan) {
        if (ei32[2 * i + 1] != 0) g_idx_is64 = 0;
    }
}

// indices -> int32 + in-degree histogram
__global__ void edge_prep_kernel(const void* __restrict__ ei_raw, int E) {
    int e = blockIdx.x * blockDim.x + threadIdx.x;
    if (e >= E) return;
    int r, c;
    if (g_idx_is64) {
        const long long* ei = (const long long*)ei_raw;
        r = (int)ei[e];
        c = (int)ei[E + e];
    } else {
        const int* ei = (const int*)ei_raw;
        r = ei[e];
        c = ei[E + e];
    }
    g_row[e] = r;
    g_col[e] = c;
    atomicAdd(&g_degi[c], 1);
}

__global__ void dinv_kernel(int N) {
    int i = blockIdx.x * blockDim.x + threadIdx.x;
    if (i < N) g_dinv[i] = rsqrtf((float)g_degi[i] + 1.0f);  // +1 self loop
}

// ---------------- prefix sum over degrees -> CSR offsets --------------------
__global__ void scan1_kernel(int N) {
    __shared__ int s[SCAN_B];
    int i = blockIdx.x * SCAN_B + threadIdx.x;
    int v = (i < N) ? g_degi[i] : 0;
    s[threadIdx.x] = v;
    __syncthreads();
    #pragma unroll
    for (int d = 1; d < SCAN_B; d <<= 1) {
        int t = (threadIdx.x >= d) ? s[threadIdx.x - d] : 0;
        __syncthreads();
        s[threadIdx.x] += t;
        __syncthreads();
    }
    if (i < N) g_off[i] = s[threadIdx.x] - v;          // exclusive
    if (threadIdx.x == SCAN_B - 1) g_bsum[blockIdx.x] = s[SCAN_B - 1];
}

__global__ void scan2_kernel(int nblk) {
    if (threadIdx.x == 0) {
        int acc = 0;
        for (int b = 0; b < nblk; b++) { int t = g_bsum[b]; g_bsum[b] = acc; acc += t; }
    }
}

__global__ void scan3_kernel(int N, int E) {
    int i = blockIdx.x * blockDim.x + threadIdx.x;
    if (i < N) {
        int o = g_off[i] + g_bsum[i >> 10];
        g_off[i] = o;
        g_cur[i] = o;
    }
    if (i == 0) g_off[N] = E;
}

// ---------------- CSR placement: csr[pos] = {row, dinv[r]*dinv[c]} ---------
__global__ void place_kernel(int E) {
    int e = blockIdx.x * blockDim.x + threadIdx.x;
    if (e >= E) return;
    int r = g_row[e];
    int c = g_col[e];
    int pos = atomicAdd(&g_cur[c], 1);
    float w = g_dinv[r] * g_dinv[c];
    g_csr[pos] = make_int2(r, __float_as_int(w));
}

// ---------------- encode: h0 = relu(x@W1 + b1) @ W2 + b2 -------------------
__global__ __launch_bounds__(256) void encode_kernel(
    const float* __restrict__ x,
    const float* __restrict__ W1, const float* __restrict__ b1,
    const float* __restrict__ W2, const float* __restrict__ b2,
    int N)
{
    __shared__ float xs[32][IN_F];   // 32 KB
    __shared__ float ts[32][H_F];    // 8 KB
    int tid  = threadIdx.x;
    int row0 = blockIdx.x * 32;

    for (int i = tid; i < 32 * (IN_F / 4); i += 256) {
        int r  = i / (IN_F / 4);
        int k4 = i % (IN_F / 4);
        float4 v = make_float4(0.f, 0.f, 0.f, 0.f);
        if (row0 + r < N)
            v = ((const float4*)x)[(size_t)(row0 + r) * (IN_F / 4) + k4];
        *(float4*)&xs[r][k4 * 4] = v;
    }
    __syncthreads();

    int c  = tid & 63;
    int rg = tid >> 6;

    float acc[8];
    float bb = b1[c];
    #pragma unroll
    for (int j = 0; j < 8; j++) acc[j] = bb;

    for (int k = 0; k < IN_F; k += 4) {
        float w0 = W1[(k + 0) * H_F + c];
        float w1 = W1[(k + 1) * H_F + c];
        float w2 = W1[(k + 2) * H_F + c];
        float w3 = W1[(k + 3) * H_F + c];
        #pragma unroll
        for (int j = 0; j < 8; j++) {
            float4 xv = *(const float4*)&xs[rg * 8 + j][k];
            acc[j] += xv.x * w0 + xv.y * w1 + xv.z * w2 + xv.w * w3;
        }
    }
    #pragma unroll
    for (int j = 0; j < 8; j++) ts[rg * 8 + j][c] = fmaxf(acc[j], 0.0f);
    __syncthreads();

    float acc2[8];
    float bb2 = b2[c];
    #pragma unroll
    for (int j = 0; j < 8; j++) acc2[j] = bb2;

    for (int k = 0; k < H_F; k += 4) {
        float w0 = W2[(k + 0) * H_F + c];
        float w1 = W2[(k + 1) * H_F + c];
        float w2 = W2[(k + 2) * H_F + c];
        float w3 = W2[(k + 3) * H_F + c];
        #pragma unroll
        for (int j = 0; j < 8; j++) {
            float4 tv = *(const float4*)&ts[rg * 8 + j][k];
            acc2[j] += tv.x * w0 + tv.y * w1 + tv.z * w2 + tv.w * w3;
        }
    }
    #pragma unroll
    for (int j = 0; j < 8; j++) {
        int r = row0 + rg * 8 + j;
        if (r < N) {
            g_A [r * H_F + c] = acc2[j];
            g_h0[r * H_F + c] = acc2[j];
        }
    }
}

// ---------------- fused gather+combine propagation step --------------------
// 16 threads per node, float4 per thread; per edge: broadcast {row,w}, gather
// float4 of src row, register-accumulate. Then dst = 0.9*(acc + dinv^2*self)
// + 0.1*h0. No atomics, no separate combine, no rezero.
template<int DIR>
__global__ __launch_bounds__(256) void gather_kernel(int N) {
    const float* src = DIR ? g_B : g_A;
    float*       dst = DIR ? g_A : g_B;

    int idx  = blockIdx.x * blockDim.x + threadIdx.x;
    int node = idx >> 4;
    if (node >= N) return;
    int f = (idx & 15) << 2;

    int beg = g_off[node];
    int end = g_off[node + 1];

    float4 acc = make_float4(0.f, 0.f, 0.f, 0.f);
    int j = beg;
    for (; j + 1 < end; j += 2) {
        int2 rw0 = g_csr[j];
        int2 rw1 = g_csr[j + 1];
        float4 v0 = __ldg((const float4*)(src + (size_t)rw0.x * H_F + f));
        float4 v1 = __ldg((const float4*)(src + (size_t)rw1.x * H_F + f));
        float w0 = __int_as_float(rw0.y);
        float w1 = __int_as_float(rw1.y);
        acc.x += w0 * v0.x + w1 * v1.x;
        acc.y += w0 * v0.y + w1 * v1.y;
        acc.z += w0 * v0.z + w1 * v1.z;
        acc.w += w0 * v0.w + w1 * v1.w;
    }
    if (j < end) {
        int2 rw = g_csr[j];
        float4 v = __ldg((const float4*)(src + (size_t)rw.x * H_F + f));
        float w = __int_as_float(rw.y);
        acc.x += w * v.x;
        acc.y += w * v.y;
        acc.z += w * v.z;
        acc.w += w * v.w;
    }

    float s  = g_dinv[node];
    float sw = s * s;
    float4 a = __ldg((const float4*)(src  + (size_t)node * H_F + f));
    float4 h = __ldg((const float4*)(g_h0 + (size_t)node * H_F + f));
    float4 o;
    o.x = 0.9f * (acc.x + sw * a.x) + 0.1f * h.x;
    o.y = 0.9f * (acc.y + sw * a.y) + 0.1f * h.y;
    o.z = 0.9f * (acc.z + sw * a.z) + 0.1f * h.z;
    o.w = 0.9f * (acc.w + sw * a.w) + 0.1f * h.w;
    *(float4*)(dst + (size_t)node * H_F + f) = o;
}

// ---------------- decode: out = h @ Wf + bf --------------------------------
__global__ __launch_bounds__(256) void decode_kernel(
    const float* __restrict__ Wf, const float* __restrict__ bf,
    float* __restrict__ out, int N)
{
    __shared__ float hs[32][H_F];
    __shared__ float wfs[H_F * OUT_F];
    __shared__ float bfs[OUT_F];
    int tid  = threadIdx.x;
    int row0 = blockIdx.x * 32;

    for (int i = tid; i < H_F * OUT_F; i += 256) wfs[i] = Wf[i];
    if (tid < OUT_F) bfs[tid] = bf[tid];
    for (int i = tid; i < 32 * (H_F / 4); i += 256) {
        int r  = i / (H_F / 4);
        int k4 = i % (H_F / 4);
        float4 v = make_float4(0.f, 0.f, 0.f, 0.f);
        if (row0 + r < N)
            v = ((const float4*)g_A)[(size_t)(row0 + r) * (H_F / 4) + k4];
        *(float4*)&hs[r][k4 * 4] = v;
    }
    __syncthreads();

    for (int e = tid; e < 32 * OUT_F; e += 256) {
        int r = e / OUT_F;
        int o = e % OUT_F;
        if (row0 + r >= N) continue;
        float acc = bfs[o];
        #pragma unroll
        for (int k = 0; k < H_F; k++) acc += hs[r][k] * wfs[k * OUT_F + o];
        out[(size_t)(row0 + r) * OUT_F + o] = acc;
    }
}

// ---------------- launch ---------------------------------------------------
extern "C" void kernel_launch(void* const* d_in, const int* in_sizes, int n_in,
                              void* d_out, int out_size) {
    const float* x  = (const float*)d_in[0];
    const void*  ei = d_in[1];
    const float* W1 = (const float*)d_in[2];
    const float* b1 = (const float*)d_in[3];
    const float* W2 = (const float*)d_in[4];
    const float* b2 = (const float*)d_in[5];
    const float* Wf = (const float*)d_in[6];
    const float* bf = (const float*)d_in[7];
    float* out = (float*)d_out;

    int N = in_sizes[0] / IN_F;   // 50000
    int E = in_sizes[1] / 2;      // 800000
    int nblk = (N + SCAN_B - 1) / SCAN_B;

    zero_kernel<<<(N + 255) / 256, 256>>>(N);
    detect_kernel<<<(100000 + 255) / 256, 256>>>((const int*)ei, E);
    edge_prep_kernel<<<(E + 255) / 256, 256>>>(ei, E);
    dinv_kernel<<<(N + 255) / 256, 256>>>(N);

    scan1_kernel<<<nblk, SCAN_B>>>(N);
    scan2_kernel<<<1, 32>>>(nblk);
    scan3_kernel<<<(N + 255) / 256, 256>>>(N, E);
    place_kernel<<<(E + 255) / 256, 256>>>(E);

    encode_kernel<<<(N + 31) / 32, 256>>>(x, W1, b1, W2, b2, N);

    int gat_blocks = (N * 16 + 255) / 256;
    for (int k = 0; k < KSTEPS; k += 2) {
        gather_kernel<0><<<gat_blocks, 256>>>(N);   // A -> B
        gather_kernel<1><<<gat_blocks, 256>>>(N);   // B -> A
    }

    decode_kernel<<<(N + 31) / 32, 256>>>(Wf, bf, out, N);
}

// round 3
// speedup vs baseline: 1.8091x; 1.0645x over previous
#include <cuda_runtime.h>
#include <cuda_fp16.h>
#include <cstdint>

#define IN_F   256
#define H_F    64
#define OUT_F  40
#define KSTEPS 10
#define MAX_N  50000
#define MAX_E  800000
#define SCAN_B 1024
#define MAX_BLK ((MAX_N + SCAN_B - 1) / SCAN_B)

// ---------------- scratch (device globals: no allocation allowed) ----------
// propagation state in fp16: one node row = 64 halves = 128 B = 1 L2 line
__device__ __align__(16) __half g_A [MAX_N * H_F];   // ping
__device__ __align__(16) __half g_B [MAX_N * H_F];   // pong
__device__ __align__(16) __half g_h0[MAX_N * H_F];   // teleport state
__device__ int   g_degi[MAX_N];
__device__ float g_dinv[MAX_N];
__device__ int   g_off [MAX_N + 1];
__device__ int   g_cur [MAX_N];
__device__ int   g_bsum[MAX_BLK];
__device__ int2  g_csr [MAX_E];    // {src row, weight bits}
__device__ int   g_row [MAX_E];
__device__ int   g_col [MAX_E];
__device__ int   g_idx_is64;

// ---------------- fp16<->fp32 helpers --------------------------------------
__device__ __forceinline__ float4 h4_to_f4(uint2 p) {
    __half2 lo = *reinterpret_cast<__half2*>(&p.x);
    __half2 hi = *reinterpret_cast<__half2*>(&p.y);
    float2 l = __half22float2(lo);
    float2 h = __half22float2(hi);
    return make_float4(l.x, l.y, h.x, h.y);
}
__device__ __forceinline__ uint2 f4_to_h4(float4 v) {
    __half2 lo = __floats2half2_rn(v.x, v.y);
    __half2 hi = __floats2half2_rn(v.z, v.w);
    uint2 r;
    r.x = *reinterpret_cast<unsigned*>(&lo);
    r.y = *reinterpret_cast<unsigned*>(&hi);
    return r;
}

// ---------------- init ------------------------------------------------------
__global__ void zero_kernel(int N) {
    int i = blockIdx.x * blockDim.x + threadIdx.x;
    if (i < N) g_degi[i] = 0;
    if (i == 0) g_idx_is64 = 1;
}

// detect int64 vs int32 edge_index: int64 values < 2^31 => odd words all 0
__global__ void detect_kernel(const int* __restrict__ ei32, int E) {
    int i = blockIdx.x * blockDim.x + threadIdx.x;
    int scan = (E < 100000) ? E : 100000;
    if (i < scan) {
        if (ei32[2 * i + 1] != 0) g_idx_is64 = 0;
    }
}

// indices -> int32 + in-degree histogram
__global__ void edge_prep_kernel(const void* __restrict__ ei_raw, int E) {
    int e = blockIdx.x * blockDim.x + threadIdx.x;
    if (e >= E) return;
    int r, c;
    if (g_idx_is64) {
        const long long* ei = (const long long*)ei_raw;
        r = (int)ei[e];
        c = (int)ei[E + e];
    } else {
        const int* ei = (const int*)ei_raw;
        r = ei[e];
        c = ei[E + e];
    }
    g_row[e] = r;
    g_col[e] = c;
    atomicAdd(&g_degi[c], 1);
}

__global__ void dinv_kernel(int N) {
    int i = blockIdx.x * blockDim.x + threadIdx.x;
    if (i < N) g_dinv[i] = rsqrtf((float)g_degi[i] + 1.0f);  // +1 self loop
}

// ---------------- prefix sum over degrees -> CSR offsets --------------------
__global__ void scan1_kernel(int N) {
    __shared__ int s[SCAN_B];
    int i = blockIdx.x * SCAN_B + threadIdx.x;
    int v = (i < N) ? g_degi[i] : 0;
    s[threadIdx.x] = v;
    __syncthreads();
    #pragma unroll
    for (int d = 1; d < SCAN_B; d <<= 1) {
        int t = (threadIdx.x >= d) ? s[threadIdx.x - d] : 0;
        __syncthreads();
        s[threadIdx.x] += t;
        __syncthreads();
    }
    if (i < N) g_off[i] = s[threadIdx.x] - v;          // exclusive
    if (threadIdx.x == SCAN_B - 1) g_bsum[blockIdx.x] = s[SCAN_B - 1];
}

// parallel exclusive scan over block sums (nblk <= 64 for our N)
__global__ void scan2_kernel(int nblk) {
    __shared__ int s[64];
    int t = threadIdx.x;
    if (nblk <= 64) {
        int v = (t < nblk) ? g_bsum[t] : 0;
        s[t] = v;
        __syncthreads();
        #pragma unroll
        for (int d = 1; d < 64; d <<= 1) {
            int u = (t >= d) ? s[t - d] : 0;
            __syncthreads();
            s[t] += u;
            __syncthreads();
        }
        if (t < nblk) g_bsum[t] = s[t] - v;   // exclusive
    } else if (t == 0) {
        int acc = 0;
        for (int b = 0; b < nblk; b++) { int u = g_bsum[b]; g_bsum[b] = acc; acc += u; }
    }
}

__global__ void scan3_kernel(int N, int E) {
    int i = blockIdx.x * blockDim.x + threadIdx.x;
    if (i < N) {
        int o = g_off[i] + g_bsum[i >> 10];
        g_off[i] = o;
        g_cur[i] = o;
    }
    if (i == 0) g_off[N] = E;
}

// ---------------- CSR placement: csr[pos] = {row, dinv[r]*dinv[c]} ---------
__global__ void place_kernel(int E) {
    int e = blockIdx.x * blockDim.x + threadIdx.x;
    if (e >= E) return;
    int r = g_row[e];
    int c = g_col[e];
    int pos = atomicAdd(&g_cur[c], 1);
    float w = g_dinv[r] * g_dinv[c];
    g_csr[pos] = make_int2(r, __float_as_int(w));
}

// ---------------- encode: h0 = relu(x@W1 + b1) @ W2 + b2 -------------------
__global__ __launch_bounds__(256) void encode_kernel(
    const float* __restrict__ x,
    const float* __restrict__ W1, const float* __restrict__ b1,
    const float* __restrict__ W2, const float* __restrict__ b2,
    int N)
{
    __shared__ float xs[32][IN_F];   // 32 KB
    __shared__ float ts[32][H_F];    // 8 KB
    int tid  = threadIdx.x;
    int row0 = blockIdx.x * 32;

    for (int i = tid; i < 32 * (IN_F / 4); i += 256) {
        int r  = i / (IN_F / 4);
        int k4 = i % (IN_F / 4);
        float4 v = make_float4(0.f, 0.f, 0.f, 0.f);
        if (row0 + r < N)
            v = ((const float4*)x)[(size_t)(row0 + r) * (IN_F / 4) + k4];
        *(float4*)&xs[r][k4 * 4] = v;
    }
    __syncthreads();

    int c  = tid & 63;
    int rg = tid >> 6;

    float acc[8];
    float bb = b1[c];
    #pragma unroll
    for (int j = 0; j < 8; j++) acc[j] = bb;

    for (int k = 0; k < IN_F; k += 4) {
        float w0 = W1[(k + 0) * H_F + c];
        float w1 = W1[(k + 1) * H_F + c];
        float w2 = W1[(k + 2) * H_F + c];
        float w3 = W1[(k + 3) * H_F + c];
        #pragma unroll
        for (int j = 0; j < 8; j++) {
            float4 xv = *(const float4*)&xs[rg * 8 + j][k];
            acc[j] += xv.x * w0 + xv.y * w1 + xv.z * w2 + xv.w * w3;
        }
    }
    #pragma unroll
    for (int j = 0; j < 8; j++) ts[rg * 8 + j][c] = fmaxf(acc[j], 0.0f);
    __syncthreads();

    float acc2[8];
    float bb2 = b2[c];
    #pragma unroll
    for (int j = 0; j < 8; j++) acc2[j] = bb2;

    for (int k = 0; k < H_F; k += 4) {
        float w0 = W2[(k + 0) * H_F + c];
        float w1 = W2[(k + 1) * H_F + c];
        float w2 = W2[(k + 2) * H_F + c];
        float w3 = W2[(k + 3) * H_F + c];
        #pragma unroll
        for (int j = 0; j < 8; j++) {
            float4 tv = *(const float4*)&ts[rg * 8 + j][k];
            acc2[j] += tv.x * w0 + tv.y * w1 + tv.z * w2 + tv.w * w3;
        }
    }
    #pragma unroll
    for (int j = 0; j < 8; j++) {
        int r = row0 + rg * 8 + j;
        if (r < N) {
            __half hv = __float2half_rn(acc2[j]);
            g_A [r * H_F + c] = hv;
            g_h0[r * H_F + c] = hv;
        }
    }
}

// ---------------- fused gather+combine propagation step (fp16 state) -------
// 16 threads per node, each owns 4 features (uint2 = 4 halves). Per edge:
// broadcast {row,w}, gather one 128B row (1 L2 line), fp32 accumulate.
// Then dst = 0.9*(acc + dinv^2*self) + 0.1*h0, stored fp16.
template<int DIR>
__global__ __launch_bounds__(256) void gather_kernel(int N) {
    const __half* src = DIR ? g_B : g_A;
    __half*       dst = DIR ? g_A : g_B;

    int idx  = blockIdx.x * blockDim.x + threadIdx.x;
    int node = idx >> 4;
    if (node >= N) return;
    int lane = idx & 15;                       // feature chunk 0..15

    const uint2* srcv = (const uint2*)src;     // row r chunk l -> srcv[r*16 + l]
    int beg = g_off[node];
    int end = g_off[node + 1];

    float4 acc = make_float4(0.f, 0.f, 0.f, 0.f);
    int j = beg;
    for (; j + 1 < end; j += 2) {
        int2 rw0 = g_csr[j];
        int2 rw1 = g_csr[j + 1];
        uint2 p0 = __ldg(&srcv[(size_t)rw0.x * 16 + lane]);
        uint2 p1 = __ldg(&srcv[(size_t)rw1.x * 16 + lane]);
        float w0 = __int_as_float(rw0.y);
        float w1 = __int_as_float(rw1.y);
        float4 v0 = h4_to_f4(p0);
        float4 v1 = h4_to_f4(p1);
        acc.x += w0 * v0.x + w1 * v1.x;
        acc.y += w0 * v0.y + w1 * v1.y;
        acc.z += w0 * v0.z + w1 * v1.z;
        acc.w += w0 * v0.w + w1 * v1.w;
    }
    if (j < end) {
        int2 rw = g_csr[j];
        uint2 p = __ldg(&srcv[(size_t)rw.x * 16 + lane]);
        float w = __int_as_float(rw.y);
        float4 v = h4_to_f4(p);
        acc.x += w * v.x;
        acc.y += w * v.y;
        acc.z += w * v.z;
        acc.w += w * v.w;
    }

    float s  = g_dinv[node];
    float sw = s * s;
    float4 a = h4_to_f4(__ldg(&srcv[(size_t)node * 16 + lane]));
    float4 h = h4_to_f4(__ldg(&((const uint2*)g_h0)[(size_t)node * 16 + lane]));
    float4 o;
    o.x = 0.9f * (acc.x + sw * a.x) + 0.1f * h.x;
    o.y = 0.9f * (acc.y + sw * a.y) + 0.1f * h.y;
    o.z = 0.9f * (acc.z + sw * a.z) + 0.1f * h.z;
    o.w = 0.9f * (acc.w + sw * a.w) + 0.1f * h.w;
    ((uint2*)dst)[(size_t)node * 16 + lane] = f4_to_h4(o);
}

// ---------------- decode: out = h @ Wf + bf --------------------------------
__global__ __launch_bounds__(256) void decode_kernel(
    const float* __restrict__ Wf, const float* __restrict__ bf,
    float* __restrict__ out, int N)
{
    __shared__ float hs[32][H_F];
    __shared__ float wfs[H_F * OUT_F];
    __shared__ float bfs[OUT_F];
    int tid  = threadIdx.x;
    int row0 = blockIdx.x * 32;

    for (int i = tid; i < H_F * OUT_F; i += 256) wfs[i] = Wf[i];
    if (tid < OUT_F) bfs[tid] = bf[tid];
    for (int i = tid; i < 32 * (H_F / 4); i += 256) {
        int r  = i / (H_F / 4);
        int k4 = i % (H_F / 4);
        float4 v = make_float4(0.f, 0.f, 0.f, 0.f);
        if (row0 + r < N)
            v = h4_to_f4(((const uint2*)g_A)[(size_t)(row0 + r) * 16 + k4]);
        *(float4*)&hs[r][k4 * 4] = v;
    }
    __syncthreads();

    for (int e = tid; e < 32 * OUT_F; e += 256) {
        int r = e / OUT_F;
        int o = e % OUT_F;
        if (row0 + r >= N) continue;
        float acc = bfs[o];
        #pragma unroll
        for (int k = 0; k < H_F; k++) acc += hs[r][k] * wfs[k * OUT_F + o];
        out[(size_t)(row0 + r) * OUT_F + o] = acc;
    }
}

// ---------------- launch ---------------------------------------------------
extern "C" void kernel_launch(void* const* d_in, const int* in_sizes, int n_in,
                              void* d_out, int out_size) {
    const float* x  = (const float*)d_in[0];
    const void*  ei = d_in[1];
    const float* W1 = (const float*)d_in[2];
    const float* b1 = (const float*)d_in[3];
    const float* W2 = (const float*)d_in[4];
    const float* b2 = (const float*)d_in[5];
    const float* Wf = (const float*)d_in[6];
    const float* bf = (const float*)d_in[7];
    float* out = (float*)d_out;

    int N = in_sizes[0] / IN_F;   // 50000
    int E = in_sizes[1] / 2;      // 800000
    int nblk = (N + SCAN_B - 1) / SCAN_B;

    zero_kernel<<<(N + 255) / 256, 256>>>(N);
    detect_kernel<<<(100000 + 255) / 256, 256>>>((const int*)ei, E);
    edge_prep_kernel<<<(E + 255) / 256, 256>>>(ei, E);
    dinv_kernel<<<(N + 255) / 256, 256>>>(N);

    scan1_kernel<<<nblk, SCAN_B>>>(N);
    scan2_kernel<<<1, 64>>>(nblk);
    scan3_kernel<<<(N + 255) / 256, 256>>>(N, E);
    place_kernel<<<(E + 255) / 256, 256>>>(E);

    encode_kernel<<<(N + 31) / 32, 256>>>(x, W1, b1, W2, b2, N);

    int gat_blocks = (N * 16 + 255) / 256;
    for (int k = 0; k < KSTEPS; k += 2) {
        gather_kernel<0><<<gat_blocks, 256>>>(N);   // A -> B
        gather_kernel<1><<<gat_blocks, 256>>>(N);   // B -> A
    }

    decode_kernel<<<(N + 31) / 32, 256>>>(Wf, bf, out, N);
}

// round 4
// speedup vs baseline: 1.9833x; 1.0963x over previous
#include <cuda_runtime.h>
#include <cuda_fp16.h>
#include <cstdint>

#define IN_F   256
#define H_F    64
#define OUT_F  40
#define KSTEPS 10
#define MAX_N  50000
#define MAX_E  800000
#define SCAN_B 1024
#define MAX_BLK ((MAX_N + SCAN_B - 1) / SCAN_B)

// ---------------- scratch (device globals: no allocation allowed) ----------
// propagation state fp16: one node row = 64 halves = 128 B = 1 L2 line
__device__ __align__(16) __half g_A [MAX_N * H_F];   // ping
__device__ __align__(16) __half g_B [MAX_N * H_F];   // pong
__device__ __align__(16) __half g_h0[MAX_N * H_F];   // teleport state
__device__ int   g_degi[MAX_N];
__device__ float g_dinv[MAX_N];
__device__ int   g_off [MAX_N + 1];
__device__ int   g_cur [MAX_N];
__device__ int   g_bsum[MAX_BLK];
__device__ int2  g_csr [MAX_E];    // {src row, weight bits}
__device__ int2  g_rc  [MAX_E];    // {row, col} staging
__device__ int   g_idx_is64;

// ---------------- fp16 helpers ---------------------------------------------
__device__ __forceinline__ void accum8(float4& lo, float4& hi, uint4 p, float w) {
    float2 f0 = __half22float2(*reinterpret_cast<__half2*>(&p.x));
    float2 f1 = __half22float2(*reinterpret_cast<__half2*>(&p.y));
    float2 f2 = __half22float2(*reinterpret_cast<__half2*>(&p.z));
    float2 f3 = __half22float2(*reinterpret_cast<__half2*>(&p.w));
    lo.x += w * f0.x; lo.y += w * f0.y; lo.z += w * f1.x; lo.w += w * f1.y;
    hi.x += w * f2.x; hi.y += w * f2.y; hi.z += w * f3.x; hi.w += w * f3.y;
}
__device__ __forceinline__ void h8_to_f8(uint4 p, float4& lo, float4& hi) {
    float2 f0 = __half22float2(*reinterpret_cast<__half2*>(&p.x));
    float2 f1 = __half22float2(*reinterpret_cast<__half2*>(&p.y));
    float2 f2 = __half22float2(*reinterpret_cast<__half2*>(&p.z));
    float2 f3 = __half22float2(*reinterpret_cast<__half2*>(&p.w));
    lo = make_float4(f0.x, f0.y, f1.x, f1.y);
    hi = make_float4(f2.x, f2.y, f3.x, f3.y);
}
__device__ __forceinline__ uint4 f8_to_h8(float4 lo, float4 hi) {
    __half2 h0 = __floats2half2_rn(lo.x, lo.y);
    __half2 h1 = __floats2half2_rn(lo.z, lo.w);
    __half2 h2 = __floats2half2_rn(hi.x, hi.y);
    __half2 h3 = __floats2half2_rn(hi.z, hi.w);
    uint4 r;
    r.x = *reinterpret_cast<unsigned*>(&h0);
    r.y = *reinterpret_cast<unsigned*>(&h1);
    r.z = *reinterpret_cast<unsigned*>(&h2);
    r.w = *reinterpret_cast<unsigned*>(&h3);
    return r;
}

// ---------------- init ------------------------------------------------------
__global__ void zero_kernel(int N) {
    int i = blockIdx.x * blockDim.x + threadIdx.x;
    if (i < N) g_degi[i] = 0;
    if (i == 0) g_idx_is64 = 1;
}

// detect int64 vs int32 edge_index: int64 values < 2^31 => odd words all 0
__global__ void detect_kernel(const int* __restrict__ ei32, int E) {
    int i = blockIdx.x * blockDim.x + threadIdx.x;
    int scan = (E < 100000) ? E : 100000;
    if (i < scan) {
        if (ei32[2 * i + 1] != 0) g_idx_is64 = 0;
    }
}

// indices -> packed int2 + in-degree histogram
__global__ void edge_prep_kernel(const void* __restrict__ ei_raw, int E) {
    int e = blockIdx.x * blockDim.x + threadIdx.x;
    if (e >= E) return;
    int r, c;
    if (g_idx_is64) {
        const long long* ei = (const long long*)ei_raw;
        r = (int)ei[e];
        c = (int)ei[E + e];
    } else {
        const int* ei = (const int*)ei_raw;
        r = ei[e];
        c = ei[E + e];
    }
    g_rc[e] = make_int2(r, c);
    atomicAdd(&g_degi[c], 1);
}

__global__ void dinv_kernel(int N) {
    int i = blockIdx.x * blockDim.x + threadIdx.x;
    if (i < N) g_dinv[i] = rsqrtf((float)g_degi[i] + 1.0f);  // +1 self loop
}

// ---------------- prefix sum over degrees -> CSR offsets --------------------
__global__ void scan1_kernel(int N) {
    __shared__ int s[SCAN_B];
    int i = blockIdx.x * SCAN_B + threadIdx.x;
    int v = (i < N) ? g_degi[i] : 0;
    s[threadIdx.x] = v;
    __syncthreads();
    #pragma unroll
    for (int d = 1; d < SCAN_B; d <<= 1) {
        int t = (threadIdx.x >= d) ? s[threadIdx.x - d] : 0;
        __syncthreads();
        s[threadIdx.x] += t;
        __syncthreads();
    }
    if (i < N) g_off[i] = s[threadIdx.x] - v;          // exclusive
    if (threadIdx.x == SCAN_B - 1) g_bsum[blockIdx.x] = s[SCAN_B - 1];
}

__global__ void scan2_kernel(int nblk) {
    __shared__ int s[64];
    int t = threadIdx.x;
    if (nblk <= 64) {
        int v = (t < nblk) ? g_bsum[t] : 0;
        s[t] = v;
        __syncthreads();
        #pragma unroll
        for (int d = 1; d < 64; d <<= 1) {
            int u = (t >= d) ? s[t - d] : 0;
            __syncthreads();
            s[t] += u;
            __syncthreads();
        }
        if (t < nblk) g_bsum[t] = s[t] - v;   // exclusive
    } else if (t == 0) {
        int acc = 0;
        for (int b = 0; b < nblk; b++) { int u = g_bsum[b]; g_bsum[b] = acc; acc += u; }
    }
}

__global__ void scan3_kernel(int N, int E) {
    int i = blockIdx.x * blockDim.x + threadIdx.x;
    if (i < N) {
        int o = g_off[i] + g_bsum[i >> 10];
        g_off[i] = o;
        g_cur[i] = o;
    }
    if (i == 0) g_off[N] = E;
}

// ---------------- CSR placement: csr[pos] = {row, dinv[r]*dinv[c]} ---------
__global__ void place_kernel(int E) {
    int e = blockIdx.x * blockDim.x + threadIdx.x;
    if (e >= E) return;
    int2 rc = g_rc[e];
    int pos = atomicAdd(&g_cur[rc.y], 1);
    float w = g_dinv[rc.x] * g_dinv[rc.y];
    g_csr[pos] = make_int2(rc.x, __float_as_int(w));
}

// ---------------- encode: h0 = relu(x@W1 + b1) @ W2 + b2 -------------------
__global__ __launch_bounds__(256) void encode_kernel(
    const float* __restrict__ x,
    const float* __restrict__ W1, const float* __restrict__ b1,
    const float* __restrict__ W2, const float* __restrict__ b2,
    int N)
{
    __shared__ float xs[32][IN_F];   // 32 KB
    __shared__ float ts[32][H_F];    // 8 KB
    int tid  = threadIdx.x;
    int row0 = blockIdx.x * 32;

    for (int i = tid; i < 32 * (IN_F / 4); i += 256) {
        int r  = i / (IN_F / 4);
        int k4 = i % (IN_F / 4);
        float4 v = make_float4(0.f, 0.f, 0.f, 0.f);
        if (row0 + r < N)
            v = ((const float4*)x)[(size_t)(row0 + r) * (IN_F / 4) + k4];
        *(float4*)&xs[r][k4 * 4] = v;
    }
    __syncthreads();

    int c  = tid & 63;
    int rg = tid >> 6;

    float acc[8];
    float bb = b1[c];
    #pragma unroll
    for (int j = 0; j < 8; j++) acc[j] = bb;

    for (int k = 0; k < IN_F; k += 4) {
        float w0 = W1[(k + 0) * H_F + c];
        float w1 = W1[(k + 1) * H_F + c];
        float w2 = W1[(k + 2) * H_F + c];
        float w3 = W1[(k + 3) * H_F + c];
        #pragma unroll
        for (int j = 0; j < 8; j++) {
            float4 xv = *(const float4*)&xs[rg * 8 + j][k];
            acc[j] += xv.x * w0 + xv.y * w1 + xv.z * w2 + xv.w * w3;
        }
    }
    #pragma unroll
    for (int j = 0; j < 8; j++) ts[rg * 8 + j][c] = fmaxf(acc[j], 0.0f);
    __syncthreads();

    float acc2[8];
    float bb2 = b2[c];
    #pragma unroll
    for (int j = 0; j < 8; j++) acc2[j] = bb2;

    for (int k = 0; k < H_F; k += 4) {
        float w0 = W2[(k + 0) * H_F + c];
        float w1 = W2[(k + 1) * H_F + c];
        float w2 = W2[(k + 2) * H_F + c];
        float w3 = W2[(k + 3) * H_F + c];
        #pragma unroll
        for (int j = 0; j < 8; j++) {
            float4 tv = *(const float4*)&ts[rg * 8 + j][k];
            acc2[j] += tv.x * w0 + tv.y * w1 + tv.z * w2 + tv.w * w3;
        }
    }
    #pragma unroll
    for (int j = 0; j < 8; j++) {
        int r = row0 + rg * 8 + j;
        if (r < N) {
            __half hv = __float2half_rn(acc2[j]);
            g_A [r * H_F + c] = hv;
            g_h0[r * H_F + c] = hv;
        }
    }
}

// ---------------- fused gather+combine propagation step --------------------
// 8 threads per node, each owns 16 B (uint4 = 8 halves). Per warp: 4 node
// edge-streams. 4-way unrolled edge loop -> 4 independent L2 gathers in
// flight per stream. fp32 accumulate, fp16 store.
template<int DIR>
__global__ __launch_bounds__(256) void gather_kernel(int N) {
    const __half* src = DIR ? g_B : g_A;
    __half*       dst = DIR ? g_A : g_B;

    int idx  = blockIdx.x * blockDim.x + threadIdx.x;
    int node = idx >> 3;
    if (node >= N) return;
    int lane = idx & 7;                        // 16B chunk 0..7

    const uint4* srcv = (const uint4*)src;     // row r chunk l -> srcv[r*8 + l]
    int beg = g_off[node];
    int end = g_off[node + 1];

    float4 alo = make_float4(0.f, 0.f, 0.f, 0.f);
    float4 ahi = make_float4(0.f, 0.f, 0.f, 0.f);

    int j = beg;
    int stop4 = beg + ((end - beg) & ~3);
    for (; j < stop4; j += 4) {
        int2 rw0 = g_csr[j];
        int2 rw1 = g_csr[j + 1];
        int2 rw2 = g_csr[j + 2];
        int2 rw3 = g_csr[j + 3];
        uint4 p0 = __ldg(&srcv[(size_t)rw0.x * 8 + lane]);
        uint4 p1 = __ldg(&srcv[(size_t)rw1.x * 8 + lane]);
        uint4 p2 = __ldg(&srcv[(size_t)rw2.x * 8 + lane]);
        uint4 p3 = __ldg(&srcv[(size_t)rw3.x * 8 + lane]);
        accum8(alo, ahi, p0, __int_as_float(rw0.y));
        accum8(alo, ahi, p1, __int_as_float(rw1.y));
        accum8(alo, ahi, p2, __int_as_float(rw2.y));
        accum8(alo, ahi, p3, __int_as_float(rw3.y));
    }
    for (; j < end; j++) {
        int2 rw = g_csr[j];
        uint4 p = __ldg(&srcv[(size_t)rw.x * 8 + lane]);
        accum8(alo, ahi, p, __int_as_float(rw.y));
    }

    float s  = g_dinv[node];
    float sw = s * s;
    float4 slo, shi, hlo, hhi;
    h8_to_f8(__ldg(&srcv[(size_t)node * 8 + lane]), slo, shi);
    h8_to_f8(__ldg(&((const uint4*)g_h0)[(size_t)node * 8 + lane]), hlo, hhi);
    float4 olo, ohi;
    olo.x = 0.9f * (alo.x + sw * slo.x) + 0.1f * hlo.x;
    olo.y = 0.9f * (alo.y + sw * slo.y) + 0.1f * hlo.y;
    olo.z = 0.9f * (alo.z + sw * slo.z) + 0.1f * hlo.z;
    olo.w = 0.9f * (alo.w + sw * slo.w) + 0.1f * hlo.w;
    ohi.x = 0.9f * (ahi.x + sw * shi.x) + 0.1f * hhi.x;
    ohi.y = 0.9f * (ahi.y + sw * shi.y) + 0.1f * hhi.y;
    ohi.z = 0.9f * (ahi.z + sw * shi.z) + 0.1f * hhi.z;
    ohi.w = 0.9f * (ahi.w + sw * shi.w) + 0.1f * hhi.w;
    ((uint4*)dst)[(size_t)node * 8 + lane] = f8_to_h8(olo, ohi);
}

// ---------------- decode: out = h @ Wf + bf --------------------------------
__global__ __launch_bounds__(256) void decode_kernel(
    const float* __restrict__ Wf, const float* __restrict__ bf,
    float* __restrict__ out, int N)
{
    __shared__ float hs[32][H_F];
    __shared__ float wfs[H_F * OUT_F];
    __shared__ float bfs[OUT_F];
    int tid  = threadIdx.x;
    int row0 = blockIdx.x * 32;

    for (int i = tid; i < H_F * OUT_F; i += 256) wfs[i] = Wf[i];
    if (tid < OUT_F) bfs[tid] = bf[tid];
    for (int i = tid; i < 32 * 8; i += 256) {
        int r  = i >> 3;
        int k8 = i & 7;
        float4 lo = make_float4(0.f, 0.f, 0.f, 0.f), hi = lo;
        if (row0 + r < N)
            h8_to_f8(((const uint4*)g_A)[(size_t)(row0 + r) * 8 + k8], lo, hi);
        *(float4*)&hs[r][k8 * 8]     = lo;
        *(float4*)&hs[r][k8 * 8 + 4] = hi;
    }
    __syncthreads();

    for (int e = tid; e < 32 * OUT_F; e += 256) {
        int r = e / OUT_F;
        int o = e % OUT_F;
        if (row0 + r >= N) continue;
        float acc = bfs[o];
        #pragma unroll
        for (int k = 0; k < H_F; k++) acc += hs[r][k] * wfs[k * OUT_F + o];
        out[(size_t)(row0 + r) * OUT_F + o] = acc;
    }
}

// ---------------- launch ---------------------------------------------------
extern "C" void kernel_launch(void* const* d_in, const int* in_sizes, int n_in,
                              void* d_out, int out_size) {
    const float* x  = (const float*)d_in[0];
    const void*  ei = d_in[1];
    const float* W1 = (const float*)d_in[2];
    const float* b1 = (const float*)d_in[3];
    const float* W2 = (const float*)d_in[4];
    const float* b2 = (const float*)d_in[5];
    const float* Wf = (const float*)d_in[6];
    const float* bf = (const float*)d_in[7];
    float* out = (float*)d_out;

    int N = in_sizes[0] / IN_F;   // 50000
    int E = in_sizes[1] / 2;      // 800000
    int nblk = (N + SCAN_B - 1) / SCAN_B;

    zero_kernel<<<(N + 255) / 256, 256>>>(N);
    detect_kernel<<<(100000 + 255) / 256, 256>>>((const int*)ei, E);
    edge_prep_kernel<<<(E + 255) / 256, 256>>>(ei, E);
    dinv_kernel<<<(N + 255) / 256, 256>>>(N);

    scan1_kernel<<<nblk, SCAN_B>>>(N);
    scan2_kernel<<<1, 64>>>(nblk);
    scan3_kernel<<<(N + 255) / 256, 256>>>(N, E);
    place_kernel<<<(E + 255) / 256, 256>>>(E);

    encode_kernel<<<(N + 31) / 32, 256>>>(x, W1, b1, W2, b2, N);

    int gat_blocks = (N * 8 + 255) / 256;
    for (int k = 0; k < KSTEPS; k += 2) {
        gather_kernel<0><<<gat_blocks, 256>>>(N);   // A -> B
        gather_kernel<1><<<gat_blocks, 256>>>(N);   // B -> A
    }

    decode_kernel<<<(N + 31) / 32, 256>>>(Wf, bf, out, N);
}